// round 5
// baseline (speedup 1.0000x reference)
#include <cuda_runtime.h>

// ---------------- problem constants ----------------
#define IN_DIM 256
#define KTOT   33152          // FEAT = 259 chunks of 128
#define NTOT   8192
#define BATCH  8
#define S_DIM  32
#define OUT_F  64

// ---------------- gemm tiling ----------------
#define CHUNK   128
#define NCHUNK  (KTOT / CHUNK)           // 259
#define KTILE   512                      // feats tile = 4 chunks
#define NTILE   ((KTOT + KTILE - 1) / KTILE)  // 65 (last tile = 3 chunks)
#define STAGES  4
#define TCOLS   4
#define WARPS   8
#define COLS_PER_BLOCK (WARPS * TCOLS)   // 32
#define GEMM_BLOCKS (NTOT / COLS_PER_BLOCK) // 256

// smem layout (floats): [0,128) mbars  [128, 128+8192) feats x2  [8320, +16384) W rings
#define SF_BASE_F   128
#define SW_BASE_F   (SF_BASE_F + 2 * BATCH * KTILE)          // 8320
#define SMEM_FLOATS (SW_BASE_F + WARPS * STAGES * TCOLS * CHUNK) // 24704
#define SMEM_BYTES  (SMEM_FLOATS * 4)                         // 98816

__device__ float g_feats[BATCH * KTOT];
__device__ float g_head [BATCH * NTOT];

using u64 = unsigned long long;
union F4U { float4 f4; u64 u[2]; float f[4]; };
union F2U { u64 u; float f[2]; };

__device__ __forceinline__ u64 ffma2(u64 a, u64 b, u64 c) {
    u64 d;
    asm("fma.rn.f32x2 %0, %1, %2, %3;" : "=l"(d) : "l"(a), "l"(b), "l"(c));
    return d;
}
__device__ __forceinline__ void mbar_init(unsigned mbar, unsigned cnt) {
    asm volatile("mbarrier.init.shared.b64 [%0], %1;" :: "r"(mbar), "r"(cnt) : "memory");
}
__device__ __forceinline__ void mbar_expect(unsigned mbar, unsigned bytes) {
    asm volatile("mbarrier.arrive.expect_tx.shared.b64 _, [%0], %1;"
                 :: "r"(mbar), "r"(bytes) : "memory");
}
__device__ __forceinline__ void bulkcp(unsigned dst, const float* src,
                                       unsigned bytes, unsigned mbar) {
    asm volatile("cp.async.bulk.shared::cta.global.mbarrier::complete_tx::bytes "
                 "[%0], [%1], %2, [%3];"
                 :: "r"(dst), "l"(src), "r"(bytes), "r"(mbar) : "memory");
}
__device__ __forceinline__ void mwait(unsigned mbar, unsigned parity) {
    asm volatile(
        "{\n\t.reg .pred P;\n"
        "WL%=:\n\t"
        "mbarrier.try_wait.parity.acquire.cta.shared::cta.b64 P, [%0], %1, 0x989680;\n\t"
        "@P bra WD%=;\n\t"
        "bra WL%=;\n"
        "WD%=:\n\t}"
        :: "r"(mbar), "r"(parity) : "memory");
}

// ---------------------------------------------------------------
// Kernel 1: build features
// ---------------------------------------------------------------
__global__ void feat_kernel(const float* __restrict__ x) {
    const int i = blockIdx.x, b = blockIdx.y, j = threadIdx.x;
    __shared__ float sx[IN_DIM];
    sx[j] = x[b * IN_DIM + j];
    __syncthreads();
    float* gb = g_feats + (size_t)b * KTOT;
    if (i == 0) gb[j] = sx[j];
    if (j >= i) {
        int off = 256 * i - (i * (i - 1)) / 2;
        gb[IN_DIM + off + (j - i)] = sx[i] * sx[j];
    }
}

// ---------------------------------------------------------------
// Kernel 2: head GEMM. Per-warp bulk-copy W pipeline (4 stages,
// warp-private mbarriers), bulk-copied double-buffered feats tiles.
// ---------------------------------------------------------------
__global__ void __launch_bounds__(WARPS * 32, 2)
gemm_kernel(const float* __restrict__ W, const float* __restrict__ bh) {
    extern __shared__ __align__(16) float smem[];
    float* sf = smem + SF_BASE_F;               // [2][8][512]
    float* sw = smem + SW_BASE_F;               // [8][4][4][128]
    const unsigned sbase = (unsigned)__cvta_generic_to_shared(smem);

    const int tid  = threadIdx.x;
    const int warp = tid >> 5;
    const int lane = tid & 31;
    const int n0   = blockIdx.x * COLS_PER_BLOCK + warp * TCOLS;

    // barrier addresses (bytes): wbar[warp][stage] = idx warp*4+stage; fbar[b] = 32+b
    const unsigned wbar0 = sbase + (unsigned)(warp * STAGES) * 8u;
    const unsigned fbar0 = sbase + 32u * 8u;
    // smem byte offsets
    const unsigned sw_my = sbase + (unsigned)(SW_BASE_F + warp * (STAGES * TCOLS * CHUNK)) * 4u;
    const unsigned sf_b  = sbase + (unsigned)SF_BASE_F * 4u;

    const float* wsrc[TCOLS];
#pragma unroll
    for (int t = 0; t < TCOLS; t++)
        wsrc[t] = W + (size_t)(n0 + t) * KTOT;

    if (tid == 0)
        for (int i = 0; i < WARPS * STAGES + 2; i++)
            mbar_init(sbase + (unsigned)i * 8u, 1);
    __syncthreads();

    // ---- prologue: W chunks 0..3 per warp; feats tiles 0,1
    if (lane == 0) {
#pragma unroll
        for (int s = 0; s < STAGES; s++) {
            mbar_expect(wbar0 + s * 8, TCOLS * CHUNK * 4);
#pragma unroll
            for (int t = 0; t < TCOLS; t++)
                bulkcp(sw_my + (unsigned)(s * TCOLS + t) * (CHUNK * 4),
                       wsrc[t] + s * CHUNK, CHUNK * 4, wbar0 + s * 8);
        }
        if (warp == 0) {
#pragma unroll
            for (int T = 0; T < 2; T++) {
                mbar_expect(fbar0 + T * 8, BATCH * KTILE * 4);
                for (int b = 0; b < BATCH; b++)
                    bulkcp(sf_b + (unsigned)(T * BATCH * KTILE + b * KTILE) * 4u,
                           g_feats + (size_t)b * KTOT + T * KTILE,
                           KTILE * 4, fbar0 + T * 8);
            }
        }
    }

    u64 acc[TCOLS][BATCH];
#pragma unroll
    for (int t = 0; t < TCOLS; t++)
#pragma unroll
        for (int b = 0; b < BATCH; b++) acc[t][b] = 0ull;

    // ---- main loop over tiles
    for (int T = 0; T < NTILE; T++) {
        if (T >= 1) {
            __syncthreads();                    // all warps done with tile T-1
            const int Tn = T + 1;
            if (Tn < NTILE && tid == 0) {       // issue feats tile T+1
                const int k0 = Tn * KTILE;
                const int rb = ((KTOT - k0 < KTILE) ? (KTOT - k0) : KTILE) * 4;
                const unsigned fb = fbar0 + (Tn & 1) * 8;
                mbar_expect(fb, BATCH * rb);
                for (int b = 0; b < BATCH; b++)
                    bulkcp(sf_b + (unsigned)(((Tn & 1) * BATCH + b) * KTILE) * 4u,
                           g_feats + (size_t)b * KTOT + k0, rb, fb);
            }
        }
        mwait(fbar0 + (T & 1) * 8, (T >> 1) & 1);
        const float* ftile = sf + (T & 1) * (BATCH * KTILE);

        const int nch = (T == NTILE - 1) ? 3 : 4;
#pragma unroll
        for (int c = 0; c < 4; c++) {
            if (c >= nch) break;
            const int kk = T * 4 + c;           // stage == c, parity == T&1
            mwait(wbar0 + c * 8, T & 1);

            const float* wp = sw + warp * (STAGES * TCOLS * CHUNK)
                                 + c * (TCOLS * CHUNK) + lane * 4;
            F4U w[TCOLS];
#pragma unroll
            for (int t = 0; t < TCOLS; t++)
                w[t].f4 = *(const float4*)(wp + t * CHUNK);

            const float* fp = ftile + c * CHUNK + lane * 4;
#pragma unroll
            for (int b = 0; b < BATCH; b++) {
                F4U fe; fe.f4 = *(const float4*)(fp + b * KTILE);
#pragma unroll
                for (int t = 0; t < TCOLS; t++) {
                    acc[t][b] = ffma2(fe.u[0], w[t].u[0], acc[t][b]);
                    acc[t][b] = ffma2(fe.u[1], w[t].u[1], acc[t][b]);
                }
            }

            // refill this stage with chunk kk+4 (all lanes done reading stage c)
            __syncwarp();
            const int p = kk + STAGES;
            if (p < NCHUNK && lane == 0) {
                mbar_expect(wbar0 + c * 8, TCOLS * CHUNK * 4);
#pragma unroll
                for (int t = 0; t < TCOLS; t++)
                    bulkcp(sw_my + (unsigned)(c * TCOLS + t) * (CHUNK * 4),
                           wsrc[t] + (size_t)p * CHUNK, CHUNK * 4, wbar0 + c * 8);
            }
        }
    }

    // ---- lane reduction + bias + store
#pragma unroll
    for (int t = 0; t < TCOLS; t++) {
        const int n = n0 + t;
        const float bias = bh[n];
#pragma unroll
        for (int b = 0; b < BATCH; b++) {
            F2U a; a.u = acc[t][b];
            float s = a.f[0] + a.f[1];
#pragma unroll
            for (int off = 16; off; off >>= 1)
                s += __shfl_xor_sync(0xffffffffu, s, off);
            if (lane == 0)
                g_head[b * NTOT + n] = s + bias;
        }
    }
}

// ---------------------------------------------------------------
// Kernel 3: output projection
// ---------------------------------------------------------------
__global__ void out_kernel(const float* __restrict__ Wout,
                           const float* __restrict__ bout,
                           float* __restrict__ out) {
    const int bs = blockIdx.x;
    const int b = bs >> 5, s = bs & 31;
    __shared__ __align__(16) float row[256];
    const int tid = threadIdx.x;

    for (int c = tid; c < 256; c += 64) {
        int h = c >> 6, d = c & 63;
        row[c] = g_head[b * NTOT + h * (S_DIM * 64) + s * 64 + d];
    }
    __syncthreads();

    float acc = bout[tid];
    const float4* wr = (const float4*)(Wout + tid * 256);
    const float4* rr = (const float4*)row;
#pragma unroll
    for (int q = 0; q < 64; q++) {
        float4 w = wr[q];
        float4 r = rr[q];
        acc += w.x * r.x + w.y * r.y + w.z * r.z + w.w * r.w;
    }
    out[bs * 64 + tid] = acc;
}

// ---------------------------------------------------------------
extern "C" void kernel_launch(void* const* d_in, const int* in_sizes, int n_in,
                              void* d_out, int out_size) {
    const float* input   = (const float*)d_in[0];
    const float* W_heads = (const float*)d_in[1];
    const float* b_heads = (const float*)d_in[2];
    const float* W_out   = (const float*)d_in[3];
    const float* b_out   = (const float*)d_in[4];
    float* out = (float*)d_out;

    cudaFuncSetAttribute(gemm_kernel,
                         cudaFuncAttributeMaxDynamicSharedMemorySize, SMEM_BYTES);

    dim3 g1(IN_DIM, BATCH);
    feat_kernel<<<g1, IN_DIM>>>(input);
    gemm_kernel<<<GEMM_BLOCKS, WARPS * 32, SMEM_BYTES>>>(W_heads, b_heads);
    out_kernel<<<BATCH * S_DIM, OUT_F>>>(W_out, b_out, out);
}

// round 6
// speedup vs baseline: 1.2803x; 1.2803x over previous
#include <cuda_runtime.h>

// ---------------- problem constants ----------------
#define IN_DIM 256
#define KTOT   33152          // FEAT = 259 chunks of 128
#define NTOT   8192
#define BATCH  8
#define S_DIM  32
#define OUT_F  64

// ---------------- gemm tiling ----------------
#define CHUNK   128
#define NCHUNK  (KTOT / CHUNK)           // 259
#define KTILE   512                      // feats tile = 4 chunks
#define NTILE   ((KTOT + KTILE - 1) / KTILE)  // 65 (last tile = 3 chunks)
#define STAGES  4
#define TCOLS   4
#define WARPS   7                        // 224 threads
#define COLS_PER_BLOCK (WARPS * TCOLS)   // 28
#define GEMM_BLOCKS 296                  // 148 SMs x 2 — perfectly uniform
#define W_STAGE_FLOATS (COLS_PER_BLOCK * CHUNK)            // 3584
#define SMEM_FLOATS (STAGES * W_STAGE_FLOATS + 2 * BATCH * KTILE) // 22528
#define SMEM_BYTES  (SMEM_FLOATS * 4)    // 90112

__device__ float g_feats[BATCH * KTOT];
__device__ float g_head [BATCH * NTOT];

using u64 = unsigned long long;
union F4U { float4 f4; u64 u[2]; float f[4]; };
union F2U { u64 u; float f[2]; };

__device__ __forceinline__ u64 ffma2(u64 a, u64 b, u64 c) {
    u64 d;
    asm("fma.rn.f32x2 %0, %1, %2, %3;" : "=l"(d) : "l"(a), "l"(b), "l"(c));
    return d;
}
__device__ __forceinline__ void cpa16(float* dst, const float* src) {
    unsigned s = (unsigned)__cvta_generic_to_shared(dst);
    asm volatile("cp.async.cg.shared.global [%0], [%1], 16;" :: "r"(s), "l"(src) : "memory");
}
__device__ __forceinline__ void cpa_commit() {
    asm volatile("cp.async.commit_group;" ::: "memory");
}
__device__ __forceinline__ void cpa_wait3() {
    asm volatile("cp.async.wait_group 3;" ::: "memory");
}

// ---------------------------------------------------------------
// Kernel 1: build features
// ---------------------------------------------------------------
__global__ void feat_kernel(const float* __restrict__ x) {
    const int i = blockIdx.x, b = blockIdx.y, j = threadIdx.x;
    __shared__ float sx[IN_DIM];
    sx[j] = x[b * IN_DIM + j];
    __syncthreads();
    float* gb = g_feats + (size_t)b * KTOT;
    if (i == 0) gb[j] = sx[j];
    if (j >= i) {
        int off = 256 * i - (i * (i - 1)) / 2;
        gb[IN_DIM + off + (j - i)] = sx[i] * sx[j];
    }
}

// ---------------------------------------------------------------
// Kernel 2: head GEMM — cp.async 4-stage W ring, 28 cols/block,
// grid 296 = 148x2 (uniform SM load). Tail cols clamped to row 8191.
// ---------------------------------------------------------------
__global__ void __launch_bounds__(WARPS * 32, 2)
gemm_kernel(const float* __restrict__ W, const float* __restrict__ bh) {
    extern __shared__ __align__(16) float smem[];
    float* sw = smem;                               // [STAGES][28][128]
    float* sf = smem + STAGES * W_STAGE_FLOATS;     // [2][8][512]

    const int tid  = threadIdx.x;
    const int warp = tid >> 5;
    const int lane = tid & 31;
    const int n0   = blockIdx.x * COLS_PER_BLOCK + warp * TCOLS;

    // W issue mapping: thread copies 4x16B of column mycol (warp-local: mycol>>2 == warp)
    const int mycol = tid >> 3;        // 0..27
    const int myq   = tid & 7;         // 0..7
    int srcrow = blockIdx.x * COLS_PER_BLOCK + mycol;
    if (srcrow > NTOT - 1) srcrow = NTOT - 1;       // tail blocks: clamp (redundant reads)
    const float* wsrc_base = W + (size_t)srcrow * KTOT + myq * 4;

    u64 acc[TCOLS][BATCH];
#pragma unroll
    for (int t = 0; t < TCOLS; t++)
#pragma unroll
        for (int b = 0; b < BATCH; b++) acc[t][b] = 0ull;

    // ---- prologue: groups 0..2 = W chunks 0..2 (+ feats tile 0 in G0)
#pragma unroll
    for (int c = 0; c < STAGES - 1; c++) {
        const float* src = wsrc_base + c * CHUNK;
        float* dst = sw + (c * COLS_PER_BLOCK + mycol) * CHUNK + myq * 4;
#pragma unroll
        for (int j = 0; j < 4; j++) cpa16(dst + j * 32, src + j * 32);
        if (c == 0) {   // feats tile 0 -> buffer 0
            for (int idx = tid; idx < BATCH * (KTILE / 4); idx += WARPS * 32) {
                int b = idx >> 7, r = idx & 127;   // KTILE/4 = 128
                cpa16(sf + b * KTILE + r * 4, g_feats + (size_t)b * KTOT + r * 4);
            }
        }
        cpa_commit();
    }
    asm volatile("cp.async.wait_group 2;" ::: "memory");  // G0 (feats t0) done
    __syncthreads();

    // ---- main loop over 259 chunks
    for (int kk = 0; kk < NCHUNK; kk++) {
        if ((kk & 3) == 0 && kk != 0)
            __syncthreads();   // tile swap: all warps done with old feats buf

        // issue W chunk kk+3
        const int p = kk + STAGES - 1;
        if (p < NCHUNK) {
            const float* src = wsrc_base + (size_t)p * CHUNK;
            float* dst = sw + ((p & 3) * COLS_PER_BLOCK + mycol) * CHUNK + myq * 4;
#pragma unroll
            for (int j = 0; j < 4; j++) cpa16(dst + j * 32, src + j * 32);
        }
        // issue feats tile (kk/4)+1 at tile starts
        if ((kk & 3) == 0) {
            const int Tn = (kk >> 2) + 1;
            if (Tn < NTILE) {
                const int k0 = Tn * KTILE;
                const int nv = (KTOT - k0 < KTILE ? KTOT - k0 : KTILE) >> 2; // 128 or 96
                float* fdst = sf + (Tn & 1) * BATCH * KTILE;
                for (int idx = tid; idx < BATCH * nv; idx += WARPS * 32) {
                    int b = idx / nv, r = idx - b * nv;
                    cpa16(fdst + b * KTILE + r * 4,
                          g_feats + (size_t)b * KTOT + k0 + r * 4);
                }
            }
        }
        cpa_commit();
        cpa_wait3();           // chunk kk resident (this thread's copies)
        __syncwarp();          // my warp's 4 cols fully visible

        // ---- compute chunk kk
        const float* wp = sw + ((kk & 3) * COLS_PER_BLOCK + warp * TCOLS) * CHUNK + lane * 4;
        F4U w[TCOLS];
#pragma unroll
        for (int t = 0; t < TCOLS; t++)
            w[t].f4 = *(const float4*)(wp + t * CHUNK);

        const float* fp = sf + ((kk >> 2) & 1) * BATCH * KTILE + (kk & 3) * CHUNK + lane * 4;
#pragma unroll
        for (int b = 0; b < BATCH; b++) {
            F4U fe; fe.f4 = *(const float4*)(fp + b * KTILE);
#pragma unroll
            for (int t = 0; t < TCOLS; t++) {
                acc[t][b] = ffma2(fe.u[0], w[t].u[0], acc[t][b]);
                acc[t][b] = ffma2(fe.u[1], w[t].u[1], acc[t][b]);
            }
        }
    }

    // ---- lane reduction + bias + store (guard tail cols)
#pragma unroll
    for (int t = 0; t < TCOLS; t++) {
        const int n = n0 + t;
        if (n < NTOT) {
            const float bias = bh[n];
#pragma unroll
            for (int b = 0; b < BATCH; b++) {
                F2U a; a.u = acc[t][b];
                float s = a.f[0] + a.f[1];
#pragma unroll
                for (int off = 16; off; off >>= 1)
                    s += __shfl_xor_sync(0xffffffffu, s, off);
                if (lane == 0)
                    g_head[b * NTOT + n] = s + bias;
            }
        }
    }
}

// ---------------------------------------------------------------
// Kernel 3: output projection
// ---------------------------------------------------------------
__global__ void out_kernel(const float* __restrict__ Wout,
                           const float* __restrict__ bout,
                           float* __restrict__ out) {
    const int bs = blockIdx.x;
    const int b = bs >> 5, s = bs & 31;
    __shared__ __align__(16) float row[256];
    const int tid = threadIdx.x;

    for (int c = tid; c < 256; c += 64) {
        int h = c >> 6, d = c & 63;
        row[c] = g_head[b * NTOT + h * (S_DIM * 64) + s * 64 + d];
    }
    __syncthreads();

    float acc = bout[tid];
    const float4* wr = (const float4*)(Wout + tid * 256);
    const float4* rr = (const float4*)row;
#pragma unroll
    for (int q = 0; q < 64; q++) {
        float4 w = wr[q];
        float4 r = rr[q];
        acc += w.x * r.x + w.y * r.y + w.z * r.z + w.w * r.w;
    }
    out[bs * 64 + tid] = acc;
}

// ---------------------------------------------------------------
extern "C" void kernel_launch(void* const* d_in, const int* in_sizes, int n_in,
                              void* d_out, int out_size) {
    const float* input   = (const float*)d_in[0];
    const float* W_heads = (const float*)d_in[1];
    const float* b_heads = (const float*)d_in[2];
    const float* W_out   = (const float*)d_in[3];
    const float* b_out   = (const float*)d_in[4];
    float* out = (float*)d_out;

    cudaFuncSetAttribute(gemm_kernel,
                         cudaFuncAttributeMaxDynamicSharedMemorySize, SMEM_BYTES);

    dim3 g1(IN_DIM, BATCH);
    feat_kernel<<<g1, IN_DIM>>>(input);
    gemm_kernel<<<GEMM_BLOCKS, WARPS * 32, SMEM_BYTES>>>(W_heads, b_heads);
    out_kernel<<<BATCH * S_DIM, OUT_F>>>(W_out, b_out, out);
}